// round 1
// baseline (speedup 1.0000x reference)
#include <cuda_runtime.h>

#define B_ 2
#define N_ 4096
#define C_ 512
#define H_ 8
#define D_ 64
#define SCALE_ 0.125f

// Scratch (allocation-free rule: __device__ globals)
__device__ float g_Q[B_*H_*N_*D_];
__device__ float g_K[B_*H_*N_*D_];
__device__ float g_V[B_*H_*N_*D_];
__device__ float g_X[B_*N_*C_];

// ---------------------------------------------------------------------------
// Projection GEMM: Out(r, c) = sum_k A(r, k) * W(c, k)   (A row-major 8192x512,
// W row-major 512x512). 64x64 tile per CTA, 256 threads, 4x4 microtile.
// Smem tiles stored transposed [k][m] so compute reads are float4 +
// conflict-free (consecutive tx -> consecutive addresses).
// Output written in (B, H, N, D) head-major layout for the attention stage.
// ---------------------------------------------------------------------------
__global__ __launch_bounds__(256) void proj_qkv_kernel(
    const float* __restrict__ qin, const float* __restrict__ kin,
    const float* __restrict__ vin, const float* __restrict__ Wq,
    const float* __restrict__ Wk,  const float* __restrict__ Wv)
{
    const int which = blockIdx.z;
    const float* A = (which == 0) ? qin : (which == 1) ? kin : vin;
    const float* W = (which == 0) ? Wq  : (which == 1) ? Wk  : Wv;
    float* Out     = (which == 0) ? g_Q : (which == 1) ? g_K : g_V;

    const int r0 = blockIdx.y * 64;   // flat row base over B*N = 8192
    const int hx = blockIdx.x;        // head index (64 cols per head)

    __shared__ float As[32 * 68];
    __shared__ float Ws[32 * 68];

    const int tid = threadIdx.x;
    const int ty = tid >> 4, tx = tid & 15;

    float acc[4][4];
    #pragma unroll
    for (int i = 0; i < 4; i++)
        #pragma unroll
        for (int j = 0; j < 4; j++) acc[i][j] = 0.f;

    for (int k0 = 0; k0 < C_; k0 += 32) {
        #pragma unroll
        for (int e = tid; e < 512; e += 256) {
            int row = e >> 3;            // 0..63
            int kq  = (e & 7) << 2;      // 0,4,...,28
            float4 a4 = *(const float4*)&A[(r0 + row) * C_ + k0 + kq];
            As[(kq + 0) * 68 + row] = a4.x;
            As[(kq + 1) * 68 + row] = a4.y;
            As[(kq + 2) * 68 + row] = a4.z;
            As[(kq + 3) * 68 + row] = a4.w;
            float4 w4 = *(const float4*)&W[(hx * 64 + row) * C_ + k0 + kq];
            Ws[(kq + 0) * 68 + row] = w4.x;
            Ws[(kq + 1) * 68 + row] = w4.y;
            Ws[(kq + 2) * 68 + row] = w4.z;
            Ws[(kq + 3) * 68 + row] = w4.w;
        }
        __syncthreads();
        #pragma unroll 8
        for (int kk = 0; kk < 32; kk++) {
            float4 a4 = *(const float4*)&As[kk * 68 + ty * 4];
            float4 b4 = *(const float4*)&Ws[kk * 68 + tx * 4];
            float av[4] = {a4.x, a4.y, a4.z, a4.w};
            float bv[4] = {b4.x, b4.y, b4.z, b4.w};
            #pragma unroll
            for (int i = 0; i < 4; i++)
                #pragma unroll
                for (int j = 0; j < 4; j++)
                    acc[i][j] = fmaf(av[i], bv[j], acc[i][j]);
        }
        __syncthreads();
    }

    #pragma unroll
    for (int i = 0; i < 4; i++) {
        int r  = r0 + ty * 4 + i;
        int bb = r >> 12;        // / N_
        int n  = r & (N_ - 1);
        float4 o4 = make_float4(acc[i][0], acc[i][1], acc[i][2], acc[i][3]);
        *(float4*)&Out[(((bb * H_ + hx) * N_) + n) * D_ + tx * 4] = o4;
    }
}

// ---------------------------------------------------------------------------
// Flash attention: per (b,h), 64 query rows per CTA, stream 64-row KV tiles,
// online softmax in fp32. Q/K stored d-major in smem ([d][row]) so the
// S-GEMM reads are float4 + conflict-free; P stored transposed [j][row].
// ---------------------------------------------------------------------------
__global__ __launch_bounds__(256) void attn_kernel()
{
    extern __shared__ float sm[];
    float* Qts = sm;                 // [64 d][68]
    float* Kts = sm + 64 * 68;       // [64 d][68]
    float* Vs  = sm + 2 * 64 * 68;   // [64 m][68]
    float* Pts = sm + 3 * 64 * 68;   // [64 j][68]

    const int bh = blockIdx.y;
    const float* Qp = g_Q + bh * (N_ * D_);
    const float* Kp = g_K + bh * (N_ * D_);
    const float* Vp = g_V + bh * (N_ * D_);
    const int n0 = blockIdx.x * 64;
    const int tid = threadIdx.x;
    const int ty = tid >> 4, tx = tid & 15;

    // Load Q tile, transposed + pre-scaled
    #pragma unroll
    for (int e = tid; e < 1024; e += 256) {
        int row = e >> 4;
        int dq  = (e & 15) << 2;
        float4 v = *(const float4*)&Qp[(n0 + row) * D_ + dq];
        Qts[(dq + 0) * 68 + row] = v.x * SCALE_;
        Qts[(dq + 1) * 68 + row] = v.y * SCALE_;
        Qts[(dq + 2) * 68 + row] = v.z * SCALE_;
        Qts[(dq + 3) * 68 + row] = v.w * SCALE_;
    }

    float m_i[4], l_i[4], o[4][4];
    #pragma unroll
    for (int i = 0; i < 4; i++) {
        m_i[i] = -1e30f;
        l_i[i] = 0.f;
        #pragma unroll
        for (int c = 0; c < 4; c++) o[i][c] = 0.f;
    }
    __syncthreads();

    for (int m0 = 0; m0 < N_; m0 += 64) {
        // Load K (transposed) and V (row-major) tiles
        #pragma unroll
        for (int e = tid; e < 1024; e += 256) {
            int row = e >> 4;
            int dq  = (e & 15) << 2;
            float4 kv = *(const float4*)&Kp[(m0 + row) * D_ + dq];
            Kts[(dq + 0) * 68 + row] = kv.x;
            Kts[(dq + 1) * 68 + row] = kv.y;
            Kts[(dq + 2) * 68 + row] = kv.z;
            Kts[(dq + 3) * 68 + row] = kv.w;
            float4 vv = *(const float4*)&Vp[(m0 + row) * D_ + dq];
            *(float4*)&Vs[row * 68 + dq] = vv;
        }
        __syncthreads();

        // S = Q K^T (scaled)
        float s[4][4];
        #pragma unroll
        for (int i = 0; i < 4; i++)
            #pragma unroll
            for (int j = 0; j < 4; j++) s[i][j] = 0.f;
        #pragma unroll 8
        for (int d = 0; d < 64; d++) {
            float4 q4 = *(const float4*)&Qts[d * 68 + ty * 4];
            float4 k4 = *(const float4*)&Kts[d * 68 + tx * 4];
            float qv[4] = {q4.x, q4.y, q4.z, q4.w};
            float kv[4] = {k4.x, k4.y, k4.z, k4.w};
            #pragma unroll
            for (int i = 0; i < 4; i++)
                #pragma unroll
                for (int j = 0; j < 4; j++)
                    s[i][j] = fmaf(qv[i], kv[j], s[i][j]);
        }

        // Online softmax (row stats reduced across the 16 tx lanes)
        #pragma unroll
        for (int i = 0; i < 4; i++) {
            float mx = fmaxf(fmaxf(s[i][0], s[i][1]), fmaxf(s[i][2], s[i][3]));
            #pragma unroll
            for (int off = 8; off >= 1; off >>= 1)
                mx = fmaxf(mx, __shfl_xor_sync(0xffffffffu, mx, off));
            float mn = fmaxf(m_i[i], mx);
            float alpha = __expf(m_i[i] - mn);
            m_i[i] = mn;
            float rs = 0.f;
            #pragma unroll
            for (int j = 0; j < 4; j++) {
                s[i][j] = __expf(s[i][j] - mn);
                rs += s[i][j];
            }
            #pragma unroll
            for (int off = 8; off >= 1; off >>= 1)
                rs += __shfl_xor_sync(0xffffffffu, rs, off);
            l_i[i] = l_i[i] * alpha + rs;
            #pragma unroll
            for (int c = 0; c < 4; c++) o[i][c] *= alpha;
            #pragma unroll
            for (int j = 0; j < 4; j++)
                Pts[(tx * 4 + j) * 68 + ty * 4 + i] = s[i][j];
        }
        __syncthreads();

        // O += P V
        #pragma unroll 8
        for (int j = 0; j < 64; j++) {
            float4 p4 = *(const float4*)&Pts[j * 68 + ty * 4];
            float4 v4 = *(const float4*)&Vs[j * 68 + tx * 4];
            float pv[4] = {p4.x, p4.y, p4.z, p4.w};
            float vv[4] = {v4.x, v4.y, v4.z, v4.w};
            #pragma unroll
            for (int i = 0; i < 4; i++)
                #pragma unroll
                for (int c = 0; c < 4; c++)
                    o[i][c] = fmaf(pv[i], vv[c], o[i][c]);
        }
        __syncthreads();
    }

    const int b = bh / H_, h = bh % H_;
    #pragma unroll
    for (int i = 0; i < 4; i++) {
        float inv = 1.f / l_i[i];
        float4 r = make_float4(o[i][0] * inv, o[i][1] * inv,
                               o[i][2] * inv, o[i][3] * inv);
        int rg = n0 + ty * 4 + i;
        *(float4*)&g_X[(b * N_ + rg) * C_ + h * D_ + tx * 4] = r;
    }
}

// ---------------------------------------------------------------------------
// Output projection: out = X @ Wp^T + bp  (row-major output)
// ---------------------------------------------------------------------------
__global__ __launch_bounds__(256) void proj_out_kernel(
    const float* __restrict__ Wp, const float* __restrict__ bp,
    float* __restrict__ out)
{
    const int r0 = blockIdx.y * 64;
    const int cb = blockIdx.x * 64;

    __shared__ float As[32 * 68];
    __shared__ float Ws[32 * 68];

    const int tid = threadIdx.x;
    const int ty = tid >> 4, tx = tid & 15;

    float acc[4][4];
    #pragma unroll
    for (int i = 0; i < 4; i++)
        #pragma unroll
        for (int j = 0; j < 4; j++) acc[i][j] = 0.f;

    for (int k0 = 0; k0 < C_; k0 += 32) {
        #pragma unroll
        for (int e = tid; e < 512; e += 256) {
            int row = e >> 3;
            int kq  = (e & 7) << 2;
            float4 a4 = *(const float4*)&g_X[(r0 + row) * C_ + k0 + kq];
            As[(kq + 0) * 68 + row] = a4.x;
            As[(kq + 1) * 68 + row] = a4.y;
            As[(kq + 2) * 68 + row] = a4.z;
            As[(kq + 3) * 68 + row] = a4.w;
            float4 w4 = *(const float4*)&Wp[(cb + row) * C_ + k0 + kq];
            Ws[(kq + 0) * 68 + row] = w4.x;
            Ws[(kq + 1) * 68 + row] = w4.y;
            Ws[(kq + 2) * 68 + row] = w4.z;
            Ws[(kq + 3) * 68 + row] = w4.w;
        }
        __syncthreads();
        #pragma unroll 8
        for (int kk = 0; kk < 32; kk++) {
            float4 a4 = *(const float4*)&As[kk * 68 + ty * 4];
            float4 b4 = *(const float4*)&Ws[kk * 68 + tx * 4];
            float av[4] = {a4.x, a4.y, a4.z, a4.w};
            float bv[4] = {b4.x, b4.y, b4.z, b4.w};
            #pragma unroll
            for (int i = 0; i < 4; i++)
                #pragma unroll
                for (int j = 0; j < 4; j++)
                    acc[i][j] = fmaf(av[i], bv[j], acc[i][j]);
        }
        __syncthreads();
    }

    float4 bb = *(const float4*)&bp[cb + tx * 4];
    float bv[4] = {bb.x, bb.y, bb.z, bb.w};
    #pragma unroll
    for (int i = 0; i < 4; i++) {
        int r = r0 + ty * 4 + i;
        float4 o4 = make_float4(acc[i][0] + bv[0], acc[i][1] + bv[1],
                                acc[i][2] + bv[2], acc[i][3] + bv[3]);
        *(float4*)&out[r * C_ + cb + tx * 4] = o4;
    }
}

extern "C" void kernel_launch(void* const* d_in, const int* in_sizes, int n_in,
                              void* d_out, int out_size)
{
    const float* query = (const float*)d_in[0];
    const float* key   = (const float*)d_in[1];
    const float* value = (const float*)d_in[2];
    const float* Wq    = (const float*)d_in[3];
    const float* Wk    = (const float*)d_in[4];
    const float* Wv    = (const float*)d_in[5];
    const float* Wp    = (const float*)d_in[6];
    const float* bp    = (const float*)d_in[7];
    float* out = (float*)d_out;

    const int attn_smem = 4 * 64 * 68 * (int)sizeof(float);  // 69632 B
    cudaFuncSetAttribute(attn_kernel,
                         cudaFuncAttributeMaxDynamicSharedMemorySize, attn_smem);

    dim3 blk(256);
    proj_qkv_kernel<<<dim3(8, 128, 3), blk>>>(query, key, value, Wq, Wk, Wv);
    attn_kernel<<<dim3(64, 16), blk, attn_smem>>>();
    proj_out_kernel<<<dim3(8, 128), blk>>>(Wp, bp, out);
}